// round 8
// baseline (speedup 1.0000x reference)
#include <cuda_runtime.h>
#include <cstdint>

#define BROWS 2048
#define NCOLS 16384
#define KITER 16
#define NTHREADS 512
#define NPK 16                 /* packed f32x2 per thread (32 elems) */
#define GRID 148
#define SHIFT 20.0f
#define ROWBYTES (NCOLS * 4)   /* 64 KB per input row */

// ---- packed f32x2 helpers ----
__device__ __forceinline__ uint64_t pk2(float lo, float hi) {
    uint64_t r; asm("mov.b64 %0,{%1,%2};" : "=l"(r) : "f"(lo), "f"(hi)); return r;
}
__device__ __forceinline__ void upk2(uint64_t v, float& lo, float& hi) {
    asm("mov.b64 {%0,%1},%2;" : "=f"(lo), "=f"(hi) : "l"(v));
}
__device__ __forceinline__ uint64_t mul2(uint64_t a, uint64_t b) {
    uint64_t r; asm("mul.rn.f32x2 %0,%1,%2;" : "=l"(r) : "l"(a), "l"(b)); return r;
}
__device__ __forceinline__ uint64_t add2(uint64_t a, uint64_t b) {
    uint64_t r; asm("add.rn.f32x2 %0,%1,%2;" : "=l"(r) : "l"(a), "l"(b)); return r;
}
__device__ __forceinline__ uint64_t fma2(uint64_t a, uint64_t b, uint64_t c) {
    uint64_t r; asm("fma.rn.f32x2 %0,%1,%2,%3;" : "=l"(r) : "l"(a), "l"(b), "l"(c)); return r;
}
__device__ __forceinline__ uint32_t smem_u32(const void* p) {
    uint32_t a; asm("{ .reg .u64 t; cvta.to.shared.u64 t, %1; cvt.u32.u64 %0, t; }" : "=r"(a) : "l"(p));
    return a;
}
__device__ __forceinline__ void bulk_g2s(uint32_t dst, const void* gsrc, uint32_t bytes, uint32_t mbar) {
    asm volatile("cp.async.bulk.shared::cta.global.mbarrier::complete_tx::bytes [%0], [%1], %2, [%3];"
                 :: "r"(dst), "l"(gsrc), "r"(bytes), "r"(mbar) : "memory");
}
__device__ __forceinline__ void mbar_init(uint32_t mbar, uint32_t cnt) {
    asm volatile("mbarrier.init.shared.b64 [%0], %1;" :: "r"(mbar), "r"(cnt) : "memory");
}
__device__ __forceinline__ void mbar_expect_tx(uint32_t mbar, uint32_t bytes) {
    asm volatile("mbarrier.arrive.expect_tx.shared.b64 _, [%0], %1;" :: "r"(mbar), "r"(bytes) : "memory");
}
__device__ __forceinline__ void mbar_wait(uint32_t mbar, uint32_t parity) {
    asm volatile(
        "{\n\t.reg .pred P;\n\t"
        "WL_%=:\n\t"
        "mbarrier.try_wait.parity.acquire.cta.shared::cta.b64 P, [%0], %1, 0x989680;\n\t"
        "@P bra.uni WD_%=;\n\t"
        "bra.uni WL_%=;\n\t"
        "WD_%=:\n\t}"
        :: "r"(mbar), "r"(parity) : "memory");
}

extern __shared__ char dynbuf[];   // [2*ROWBYTES]: scores half | g half

// Consume smem slots (slot, slot+1) -> e2n packed + packed S/Q accumulators.
#define CONSUME2(slot, e2n)                                                   \
    do {                                                                      \
        _Pragma("unroll")                                                     \
        for (int j = 0; j < 2; j++) {                                         \
            int i4 = tid + ((slot) + j) * NTHREADS;                           \
            float4 a = reinterpret_cast<const float4*>(bufS)[i4];             \
            float4 b = reinterpret_cast<const float4*>(bufG)[i4];             \
            float q0 = __expf(a.x + b.x - SHIFT);                             \
            float q1 = __expf(a.y + b.y - SHIFT);                             \
            float q2 = __expf(a.z + b.z - SHIFT);                             \
            float q3 = __expf(a.w + b.w - SHIFT);                             \
            uint64_t p0 = pk2(q0, q1), p1 = pk2(q2, q3);                      \
            e2n[((slot) + j) * 2]     = p0;                                   \
            e2n[((slot) + j) * 2 + 1] = p1;                                   \
            SnP = add2(SnP, p0); SnP = add2(SnP, p1);                         \
            QnP = fma2(p0, p0, QnP); QnP = fma2(p1, p1, QnP);                 \
        }                                                                     \
    } while (0)

// One 2-iteration deflation group: block-reduce (S,Q), apply i0 then i1.
// DOACC=0 skips next-group moment accumulation (last group).
#define GROUP(par, DOACC)                                                     \
    do {                                                                      \
        float s1 = S, q1 = Q;                                                 \
        _Pragma("unroll")                                                     \
        for (int o = 16; o; o >>= 1) {                                        \
            s1 += __shfl_xor_sync(0xffffffffu, s1, o);                        \
            q1 += __shfl_xor_sync(0xffffffffu, q1, o);                        \
        }                                                                     \
        float2* rb = red[par];                                                \
        if (l == 0) rb[w] = make_float2(s1, q1);                              \
        __syncthreads();                                                      \
        float2 pp = rb[l & 15];                                               \
        float Sb = pp.x, Qb = pp.y;                                           \
        _Pragma("unroll")                                                     \
        for (int o = 8; o; o >>= 1) {                                         \
            Sb += __shfl_xor_sync(0xffffffffu, Sb, o);                        \
            Qb += __shfl_xor_sync(0xffffffffu, Qb, o);                        \
        }                                                                     \
        const float i0 = __fdividef(c, Sb);                                   \
        const float S1 = fmaf(-i0, Qb, Sb);                                   \
        const float i1 = __fdividef(c, S1);                                   \
        const uint64_t ninv0 = pk2(-i0, -i0);                                 \
        const uint64_t ninv1 = pk2(-i1, -i1);                                 \
        _Pragma("unroll")                                                     \
        for (int pq = 0; pq < NPK; pq++) {                                    \
            uint64_t ohn = mul2(e2[pq], ninv0);                               \
            k2[pq] = fma2(ohn, NEG1, k2[pq]);                                 \
            e2[pq] = fma2(ohn, e2[pq], e2[pq]);                               \
        }                                                                     \
        uint64_t accS = 0ULL, accQ = 0ULL;                                    \
        _Pragma("unroll")                                                     \
        for (int pq = 0; pq < NPK; pq++) {                                    \
            uint64_t ohn = mul2(e2[pq], ninv1);                               \
            k2[pq] = fma2(ohn, NEG1, k2[pq]);                                 \
            e2[pq] = fma2(ohn, e2[pq], e2[pq]);                               \
            if (DOACC) { accS = add2(accS, e2[pq]);                           \
                         accQ = fma2(e2[pq], e2[pq], accQ); }                 \
        }                                                                     \
        if (DOACC) {                                                          \
            float h0, h1;                                                     \
            upk2(accS, h0, h1); S = h0 + h1;                                  \
            upk2(accQ, h0, h1); Q = h0 + h1;                                  \
        }                                                                     \
    } while (0)

__global__ void __launch_bounds__(NTHREADS, 1)
subset_op_kernel(const float* __restrict__ scores,
                 const float* __restrict__ gnoise,
                 float* __restrict__ out) {
    __shared__ float2 red[2][16];
    __shared__ alignas(8) unsigned long long mbar_s;

    const int tid = threadIdx.x;
    const int w = tid >> 5, l = tid & 31;
    const uint32_t mbar = smem_u32(&mbar_s);
    const uint32_t bufa = smem_u32(dynbuf);
    const float* bufS = (const float*)dynbuf;
    const float* bufG = (const float*)(dynbuf + ROWBYTES);

    const uint64_t NEG1 = 0xBF800000BF800000ULL;
    const float c = 0.999999f;   // inv = c/sum keeps onehot < 1 (replaces EPS clamp)

    if (tid == 0) mbar_init(mbar, 1);
    __syncthreads();

    int row = blockIdx.x;
    if (tid == 0) {              // prefetch first row
        mbar_expect_tx(mbar, 2 * ROWBYTES);
        bulk_g2s(bufa,            scores + (size_t)row * NCOLS, ROWBYTES, mbar);
        bulk_g2s(bufa + ROWBYTES, gnoise + (size_t)row * NCOLS, ROWBYTES, mbar);
    }
    int ph = 0;

    uint64_t e2[NPK], k2[NPK], e2n[NPK];
    float S, Q;

    // ---- full prologue for the first row ----
    {
        mbar_wait(mbar, ph); ph ^= 1;
        uint64_t SnP = 0ULL, QnP = 0ULL;
        CONSUME2(0, e2); CONSUME2(2, e2); CONSUME2(4, e2); CONSUME2(6, e2);
        float h0, h1;
        upk2(SnP, h0, h1); S = h0 + h1;
        upk2(QnP, h0, h1); Q = h0 + h1;
    }

    for (; row < BROWS; row += GRID) {
        const bool has_next = (row + GRID) < BROWS;

#pragma unroll
        for (int i = 0; i < NPK; i++) k2[i] = 0ULL;
        uint64_t SnP = 0ULL, QnP = 0ULL;

        __syncthreads();   // all reads of dynbuf (prev row's chunks / prologue) done
        if (has_next && tid == 0) {
            mbar_expect_tx(mbar, 2 * ROWBYTES);
            bulk_g2s(bufa,            scores + (size_t)(row + GRID) * NCOLS, ROWBYTES, mbar);
            bulk_g2s(bufa + ROWBYTES, gnoise + (size_t)(row + GRID) * NCOLS, ROWBYTES, mbar);
        }

        // ---- groups 0-3 (TMA for next row in flight underneath) ----
#pragma unroll 1
        for (int g = 0; g < 4; g++) GROUP(g & 1, 1);

        // ---- wait for next row's data, then groups 4-7 with interleaved
        //      next-row prologue chunks filling the reduction-stall shadow ----
        if (has_next) { mbar_wait(mbar, ph); ph ^= 1; }

        GROUP(0, 1); if (has_next) CONSUME2(0, e2n);
        GROUP(1, 1); if (has_next) CONSUME2(2, e2n);
        GROUP(0, 1); if (has_next) CONSUME2(4, e2n);
        GROUP(1, 0); if (has_next) CONSUME2(6, e2n);

        // ---- store khot (coalesced float4) ----
        float* orow = out + (size_t)row * NCOLS;
#pragma unroll
        for (int i = 0; i < 8; i++) {
            float4 v;
            upk2(k2[2*i],   v.x, v.y);
            upk2(k2[2*i+1], v.z, v.w);
            reinterpret_cast<float4*>(orow)[tid + i * NTHREADS] = v;
        }

        // ---- promote next row's state ----
#pragma unroll
        for (int i = 0; i < NPK; i++) e2[i] = e2n[i];
        float h0, h1;
        upk2(SnP, h0, h1); S = h0 + h1;
        upk2(QnP, h0, h1); Q = h0 + h1;
    }
}

extern "C" void kernel_launch(void* const* d_in, const int* in_sizes, int n_in,
                              void* d_out, int out_size) {
    const float* scores = (const float*)d_in[0];
    const float* g      = (const float*)d_in[1];
    float* out          = (float*)d_out;
    cudaFuncSetAttribute(subset_op_kernel,
                         cudaFuncAttributeMaxDynamicSharedMemorySize, 2 * ROWBYTES);
    subset_op_kernel<<<GRID, NTHREADS, 2 * ROWBYTES>>>(scores, g, out);
}